// round 1
// baseline (speedup 1.0000x reference)
#include <cuda_runtime.h>

// Problem constants
#define T_TOK 16384   // B*S = 8*2048
#define H_DIM 512
#define M_MEM 4096
#define INV_TEMP 10.0f

// ---------------------------------------------------------------------------
// Scratch (static device globals; no allocations anywhere)
// ---------------------------------------------------------------------------
__device__ float g_q[(size_t)T_TOK * H_DIM];        // 32 MB  q projection -> normalized in place
__device__ float g_mkn[(size_t)M_MEM * H_DIM];      // 8 MB   normalized memory keys
__device__ float g_w2[(size_t)M_MEM * H_DIM];       // 8 MB   W2 = mv @ Wo^T
__device__ float g_scores[(size_t)T_TOK * M_MEM];   // 256 MB scores -> attn in place

// ---------------------------------------------------------------------------
// Row L2-style normalize: out[r] = in[r] * rsqrt(sum(in[r]^2) + 1e-6)
// One block (128 threads) per row of 512 floats (1 float4 per thread).
// ---------------------------------------------------------------------------
__global__ void rownorm_kernel(const float* __restrict__ in, float* __restrict__ out)
{
    __shared__ float sh[4];
    const int row = blockIdx.x;
    const int tid = threadIdx.x;
    const float4* pi = (const float4*)(in + (size_t)row * H_DIM);
    float4 v = pi[tid];
    float s = v.x * v.x + v.y * v.y + v.z * v.z + v.w * v.w;
#pragma unroll
    for (int o = 16; o; o >>= 1) s += __shfl_xor_sync(0xffffffffu, s, o);
    if ((tid & 31) == 0) sh[tid >> 5] = s;
    __syncthreads();
    float tot = sh[0] + sh[1] + sh[2] + sh[3];
    float r = rsqrtf(tot + 1e-6f);
    float4 o4 = make_float4(v.x * r, v.y * r, v.z * r, v.w * r);
    ((float4*)(out + (size_t)row * H_DIM))[tid] = o4;
}

// ---------------------------------------------------------------------------
// Tiled SGEMM: C[M,N] = A[M,K] @ op(B)
//   BT=true : B is [N,K] row-major (C = A @ B^T)
//   BT=false: B is [K,N] row-major (C = A @ B)
// BM=BN=128, BK=16, 256 threads, 8x8 per-thread microtile.
// EPI: 0 = plain, 1 = += bias[n], 2 = masked scale (scores epilogue)
// Requires M%128==0, N%128==0, K%16==0 (holds for all call sites).
// ---------------------------------------------------------------------------
template <int EPI, bool BT>
__global__ __launch_bounds__(256, 2)
void gemm_kernel(const float* __restrict__ A, const float* __restrict__ B,
                 float* __restrict__ C, int M, int N, int K,
                 const float* __restrict__ bias, const int* __restrict__ usage)
{
    __shared__ float As[16][132];
    __shared__ float Bs[16][132];

    const int t  = threadIdx.x;
    const int m0 = blockIdx.y << 7;
    const int n0 = blockIdx.x << 7;
    const int tx = t & 15;          // 16 columns of 8
    const int ty = t >> 4;          // 16 rows of 8

    float acc[8][8];
#pragma unroll
    for (int i = 0; i < 8; i++)
#pragma unroll
        for (int j = 0; j < 8; j++) acc[i][j] = 0.0f;

    const int arow  = t >> 2;           // 0..63
    const int ac4   = (t & 3) << 2;     // 0,4,8,12
    const int bkrow = t >> 5;           // 0..7   (NN B load)
    const int bc4   = (t & 31) << 2;    // 0..124 (NN B load)

    for (int k0 = 0; k0 < K; k0 += 16) {
        // A tile: 128 rows x 16 cols, stored transposed As[k][m]
#pragma unroll
        for (int i = 0; i < 2; i++) {
            int r = arow + (i << 6);
            float4 a = *(const float4*)(A + (size_t)(m0 + r) * K + k0 + ac4);
            As[ac4 + 0][r] = a.x; As[ac4 + 1][r] = a.y;
            As[ac4 + 2][r] = a.z; As[ac4 + 3][r] = a.w;
        }
        if (BT) {
            // B tile from [N,K]: same pattern as A, rows are n
#pragma unroll
            for (int i = 0; i < 2; i++) {
                int r = arow + (i << 6);
                float4 b = *(const float4*)(B + (size_t)(n0 + r) * K + k0 + ac4);
                Bs[ac4 + 0][r] = b.x; Bs[ac4 + 1][r] = b.y;
                Bs[ac4 + 2][r] = b.z; Bs[ac4 + 3][r] = b.w;
            }
        } else {
            // B tile from [K,N]: direct (k-major rows), coalesced float4
#pragma unroll
            for (int i = 0; i < 2; i++) {
                int kr = bkrow + (i << 3);
                float4 b = *(const float4*)(B + (size_t)(k0 + kr) * N + n0 + bc4);
                *(float4*)&Bs[kr][bc4] = b;
            }
        }
        __syncthreads();

#pragma unroll
        for (int kk = 0; kk < 16; kk++) {
            float4 a0 = *(const float4*)&As[kk][(ty << 3) + 0];
            float4 a1 = *(const float4*)&As[kk][(ty << 3) + 4];
            float4 b0 = *(const float4*)&Bs[kk][(tx << 3) + 0];
            float4 b1 = *(const float4*)&Bs[kk][(tx << 3) + 4];
            float ra[8] = {a0.x, a0.y, a0.z, a0.w, a1.x, a1.y, a1.z, a1.w};
            float rb[8] = {b0.x, b0.y, b0.z, b0.w, b1.x, b1.y, b1.z, b1.w};
#pragma unroll
            for (int i = 0; i < 8; i++)
#pragma unroll
                for (int j = 0; j < 8; j++)
                    acc[i][j] = fmaf(ra[i], rb[j], acc[i][j]);
        }
        __syncthreads();
    }

    // Epilogue
    float bb[8];
    int   uu[8];
    if (EPI == 1) {
#pragma unroll
        for (int j = 0; j < 8; j++) bb[j] = bias[n0 + (tx << 3) + j];
    }
    if (EPI == 2) {
#pragma unroll
        for (int j = 0; j < 8; j++) uu[j] = usage[n0 + (tx << 3) + j];
    }
#pragma unroll
    for (int i = 0; i < 8; i++) {
        float v[8];
#pragma unroll
        for (int j = 0; j < 8; j++) {
            float x = acc[i][j];
            if (EPI == 1) x += bb[j];
            if (EPI == 2) x = (uu[j] > 0) ? x * INV_TEMP : -1e9f;
            v[j] = x;
        }
        float* cp = C + (size_t)(m0 + (ty << 3) + i) * N + n0 + (tx << 3);
        *(float4*)(cp + 0) = make_float4(v[0], v[1], v[2], v[3]);
        *(float4*)(cp + 4) = make_float4(v[4], v[5], v[6], v[7]);
    }
}

// ---------------------------------------------------------------------------
// Row softmax over M=4096, in place. One block (256 threads) per row.
// Entire row lives in registers (16 floats/thread) -> single HBM read + write.
// ---------------------------------------------------------------------------
__global__ void softmax_kernel(float* __restrict__ scores)
{
    __shared__ float sh[8];
    const int tid = threadIdx.x;
    float4* p = (float4*)(scores + (size_t)blockIdx.x * M_MEM);

    float4 v[4];
    float mx = -3.402823466e38f;
#pragma unroll
    for (int i = 0; i < 4; i++) {
        v[i] = p[tid + (i << 8)];
        mx = fmaxf(mx, fmaxf(fmaxf(v[i].x, v[i].y), fmaxf(v[i].z, v[i].w)));
    }
#pragma unroll
    for (int o = 16; o; o >>= 1) mx = fmaxf(mx, __shfl_xor_sync(0xffffffffu, mx, o));
    if ((tid & 31) == 0) sh[tid >> 5] = mx;
    __syncthreads();
    mx = sh[0];
#pragma unroll
    for (int i = 1; i < 8; i++) mx = fmaxf(mx, sh[i]);
    __syncthreads();

    float s = 0.0f;
#pragma unroll
    for (int i = 0; i < 4; i++) {
        v[i].x = __expf(v[i].x - mx);
        v[i].y = __expf(v[i].y - mx);
        v[i].z = __expf(v[i].z - mx);
        v[i].w = __expf(v[i].w - mx);
        s += v[i].x + v[i].y + v[i].z + v[i].w;
    }
#pragma unroll
    for (int o = 16; o; o >>= 1) s += __shfl_xor_sync(0xffffffffu, s, o);
    if ((tid & 31) == 0) sh[tid >> 5] = s;
    __syncthreads();
    float tot = sh[0];
#pragma unroll
    for (int i = 1; i < 8; i++) tot += sh[i];
    float inv = 1.0f / tot;

#pragma unroll
    for (int i = 0; i < 4; i++)
        p[tid + (i << 8)] = make_float4(v[i].x * inv, v[i].y * inv,
                                        v[i].z * inv, v[i].w * inv);
}

// ---------------------------------------------------------------------------
// Launch: all on the default stream, fully graph-capturable.
// Pipeline:
//   mk_n = rownorm(memory_keys)
//   W2   = mv @ Wo^T                       (folds out-projection into retrieval)
//   q    = hidden @ Wk^T + bk ; q = rownorm(q)
//   S    = mask_scale(q @ mk_n^T)          -> softmax in place -> attn
//   out  = attn @ W2 + bo
// ---------------------------------------------------------------------------
extern "C" void kernel_launch(void* const* d_in, const int* in_sizes, int n_in,
                              void* d_out, int out_size)
{
    const float* hidden = (const float*)d_in[0];
    const float* mk     = (const float*)d_in[1];
    const float* mv     = (const float*)d_in[2];
    const float* Wk     = (const float*)d_in[3];
    const float* bk     = (const float*)d_in[4];
    const float* Wo     = (const float*)d_in[5];
    const float* bo     = (const float*)d_in[6];
    const int*   usage  = (const int*)d_in[7];
    float* out = (float*)d_out;

    float *qp, *mknp, *w2p, *scp;
    cudaGetSymbolAddress((void**)&qp,   g_q);
    cudaGetSymbolAddress((void**)&mknp, g_mkn);
    cudaGetSymbolAddress((void**)&w2p,  g_w2);
    cudaGetSymbolAddress((void**)&scp,  g_scores);

    // 1. normalize memory keys
    rownorm_kernel<<<M_MEM, 128>>>(mk, mknp);

    // 2. W2 = mv @ Wo^T  (M=4096, N=512, K=512)
    gemm_kernel<0, true><<<dim3(H_DIM / 128, M_MEM / 128), 256>>>(
        mv, Wo, w2p, M_MEM, H_DIM, H_DIM, nullptr, nullptr);

    // 3. q = hidden @ Wk^T + bk  (M=16384, N=512, K=512)
    gemm_kernel<1, true><<<dim3(H_DIM / 128, T_TOK / 128), 256>>>(
        hidden, Wk, qp, T_TOK, H_DIM, H_DIM, bk, nullptr);

    // 4. normalize q in place
    rownorm_kernel<<<T_TOK, 128>>>(qp, qp);

    // 5. scores = mask_scale(q_n @ mk_n^T)  (M=16384, N=4096, K=512)
    gemm_kernel<2, true><<<dim3(M_MEM / 128, T_TOK / 128), 256>>>(
        qp, mknp, scp, T_TOK, M_MEM, H_DIM, nullptr, usage);

    // 6. softmax rows in place
    softmax_kernel<<<T_TOK, 256>>>(scp);

    // 7. out = attn @ W2 + bo  (M=16384, N=512, K=4096)
    gemm_kernel<1, false><<<dim3(H_DIM / 128, T_TOK / 128), 256>>>(
        scp, w2p, out, T_TOK, H_DIM, M_MEM, bo, nullptr);
}

// round 3
// speedup vs baseline: 2.3797x; 2.3797x over previous
#include <cuda_runtime.h>
#include <cuda_bf16.h>
#include <cstdint>

#define T_TOK 16384
#define H_DIM 512
#define M_MEM 4096
#define INV_TEMP 10.0f

// ---------------------------------------------------------------------------
// Scratch (static device globals; no allocations anywhere)
// ---------------------------------------------------------------------------
__device__ __nv_bfloat16 g_hid_hi[(size_t)T_TOK * H_DIM];
__device__ __nv_bfloat16 g_hid_lo[(size_t)T_TOK * H_DIM];
__device__ __nv_bfloat16 g_wk_hi[(size_t)H_DIM * H_DIM];
__device__ __nv_bfloat16 g_wk_lo[(size_t)H_DIM * H_DIM];
__device__ __nv_bfloat16 g_mk_hi[(size_t)M_MEM * H_DIM];
__device__ __nv_bfloat16 g_mk_lo[(size_t)M_MEM * H_DIM];
__device__ float         g_w2t[(size_t)H_DIM * M_MEM];      // W2T[h,m] = sum_v Wo[h,v] mv[m,v]
__device__ __nv_bfloat16 g_w2t_hi[(size_t)H_DIM * M_MEM];
__device__ __nv_bfloat16 g_w2t_lo[(size_t)H_DIM * M_MEM];
__device__ float         g_q[(size_t)T_TOK * H_DIM];
__device__ __nv_bfloat16 g_q_hi[(size_t)T_TOK * H_DIM];
__device__ __nv_bfloat16 g_q_lo[(size_t)T_TOK * H_DIM];
__device__ float         g_scores[(size_t)T_TOK * M_MEM];
__device__ __nv_bfloat16 g_attn_hi[(size_t)T_TOK * M_MEM];
__device__ __nv_bfloat16 g_attn_lo[(size_t)T_TOK * M_MEM];

// ---------------------------------------------------------------------------
// Helpers (baseline PTX only: cp.async / ldmatrix / mma.sync — no 'a' features)
// ---------------------------------------------------------------------------
__device__ __forceinline__ uint32_t su32(const void* p) {
    return (uint32_t)__cvta_generic_to_shared(p);
}
__device__ __forceinline__ void cp16(uint32_t dst, const void* src) {
    asm volatile("cp.async.cg.shared.global [%0], [%1], 16;\n" :: "r"(dst), "l"(src) : "memory");
}
__device__ __forceinline__ void cp_commit() { asm volatile("cp.async.commit_group;\n" ::: "memory"); }
__device__ __forceinline__ void cp_wait1()  { asm volatile("cp.async.wait_group 1;\n" ::: "memory"); }

__device__ __forceinline__ void ldsm_x4(uint32_t* r, uint32_t addr) {
    asm volatile("ldmatrix.sync.aligned.m8n8.x4.shared.b16 {%0,%1,%2,%3}, [%4];"
                 : "=r"(r[0]), "=r"(r[1]), "=r"(r[2]), "=r"(r[3]) : "r"(addr));
}
__device__ __forceinline__ void mma16816(float* c, const uint32_t* a, const uint32_t* b) {
    asm volatile(
        "mma.sync.aligned.m16n8k16.row.col.f32.bf16.bf16.f32 "
        "{%0,%1,%2,%3}, {%4,%5,%6,%7}, {%8,%9}, {%0,%1,%2,%3};"
        : "+f"(c[0]), "+f"(c[1]), "+f"(c[2]), "+f"(c[3])
        : "r"(a[0]), "r"(a[1]), "r"(a[2]), "r"(a[3]), "r"(b[0]), "r"(b[1]));
}

__device__ __forceinline__ void split1(float x, __nv_bfloat16& h, __nv_bfloat16& l) {
    h = __float2bfloat16(x);
    l = __float2bfloat16(x - __bfloat162float(h));
}

// ---------------------------------------------------------------------------
// HMMA GEMM:  C[M,N] = split(A) @ split(B)^T   (A:[M,K], B:[N,K], bf16 hi/lo)
// 128x128 CTA tile, 8 warps (2x4) of 64x32, BK=64, 3-stage cp.async pipeline.
// Computes Ah*Bh + Ah*Bl + Al*Bh with fp32 accumulators.
// EPI: 1 = +bias[n], 2 = masked scale (scores). Requires M,N % 128 == 0, K % 64 == 0.
// ---------------------------------------------------------------------------
#define BK      64
#define TROW    144                    // 128B data + 16B pad per row
#define TILE_SZ (128 * TROW)           // 18432 B
#define STG_SZ  (4 * TILE_SZ)          // Ah, Al, Bh, Bl
#define MM_SMEM (3 * STG_SZ)           // 221184 B

__device__ __forceinline__ void load_chunk(uint32_t sb, int stage,
    const __nv_bfloat16* __restrict__ Ah, const __nv_bfloat16* __restrict__ Al,
    const __nv_bfloat16* __restrict__ Bh, const __nv_bfloat16* __restrict__ Bl,
    int K, int m0, int n0, int k0, int t)
{
    const uint32_t st = sb + (uint32_t)stage * STG_SZ;
    const __nv_bfloat16* gp[4] = {Ah, Al, Bh, Bl};
    const int rb[4] = {m0, m0, n0, n0};
#pragma unroll
    for (int tile = 0; tile < 4; tile++) {
        const __nv_bfloat16* g = gp[tile];
        const int r0 = rb[tile];
#pragma unroll
        for (int i = 0; i < 4; i++) {
            const int idx = (i << 8) + t;          // 0..1023
            const int row = idx >> 3, j = idx & 7; // 8 x 16B per 128B row
            cp16(st + (uint32_t)tile * TILE_SZ + row * TROW + j * 16,
                 g + (size_t)(r0 + row) * K + k0 + (j << 3));
        }
    }
}

template <int EPI>
__global__ __launch_bounds__(256, 1)
void mm_gemm(const __nv_bfloat16* __restrict__ Ah, const __nv_bfloat16* __restrict__ Al,
             const __nv_bfloat16* __restrict__ Bh, const __nv_bfloat16* __restrict__ Bl,
             float* __restrict__ C, int Ntot, int K,
             const float* __restrict__ bias, const int* __restrict__ usage)
{
    extern __shared__ char smem[];
    const uint32_t sb = su32(smem);
    const int t   = threadIdx.x;
    const int wid = t >> 5, l = t & 31;
    const int wm  = wid & 1;            // 2 warp-rows (64 m each)
    const int wn  = wid >> 1;           // 4 warp-cols (32 n each)
    const int m0  = blockIdx.y << 7, n0 = blockIdx.x << 7;

    // lane-dependent ldmatrix base offsets (bytes) inside a tile
    const uint32_t aoff = (uint32_t)(wm * 64 + (l & 7) + ((l >> 3) & 1) * 8) * TROW
                        + ((l >> 4) & 1) * 16;
    const uint32_t boff = (uint32_t)(wn * 32 + (l & 7) + ((l >> 4) & 1) * 8) * TROW
                        + ((l >> 3) & 1) * 16;

    float acc[4][4][4];
#pragma unroll
    for (int mf = 0; mf < 4; mf++)
#pragma unroll
        for (int nf = 0; nf < 4; nf++)
#pragma unroll
            for (int i = 0; i < 4; i++) acc[mf][nf][i] = 0.0f;

    const int nch = K / BK;

    load_chunk(sb, 0, Ah, Al, Bh, Bl, K, m0, n0, 0, t);  cp_commit();
    load_chunk(sb, 1, Ah, Al, Bh, Bl, K, m0, n0, BK, t); cp_commit();

    for (int c = 0; c < nch; c++) {
        cp_wait1();
        __syncthreads();
        if (c + 2 < nch)
            load_chunk(sb, (c + 2) % 3, Ah, Al, Bh, Bl, K, m0, n0, (c + 2) * BK, t);
        cp_commit();

        const uint32_t st = sb + (uint32_t)(c % 3) * STG_SZ;
#pragma unroll
        for (int ks = 0; ks < 4; ks++) {
            uint32_t ah[4][4], al[4][4];
#pragma unroll
            for (int mf = 0; mf < 4; mf++) {
                ldsm_x4(ah[mf], st + 0 * TILE_SZ + aoff + mf * (16 * TROW) + ks * 32);
                ldsm_x4(al[mf], st + 1 * TILE_SZ + aoff + mf * (16 * TROW) + ks * 32);
            }
            uint32_t bh[2][4], bl[2][4];
#pragma unroll
            for (int nf2 = 0; nf2 < 2; nf2++) {
                ldsm_x4(bh[nf2], st + 2 * TILE_SZ + boff + nf2 * (16 * TROW) + ks * 32);
                ldsm_x4(bl[nf2], st + 3 * TILE_SZ + boff + nf2 * (16 * TROW) + ks * 32);
            }
#pragma unroll
            for (int mf = 0; mf < 4; mf++)
#pragma unroll
                for (int nf = 0; nf < 4; nf++) {
                    const uint32_t* bhp = &bh[nf >> 1][(nf & 1) * 2];
                    const uint32_t* blp = &bl[nf >> 1][(nf & 1) * 2];
                    mma16816(acc[mf][nf], ah[mf], bhp);
                    mma16816(acc[mf][nf], ah[mf], blp);
                    mma16816(acc[mf][nf], al[mf], bhp);
                }
        }
    }

    // Epilogue: c-frag -> C. c0,c1 at (row, col..col+1); c2,c3 at (row+8, ...)
#pragma unroll
    for (int mf = 0; mf < 4; mf++) {
        const int r0 = m0 + wm * 64 + mf * 16 + (l >> 2);
#pragma unroll
        for (int nf = 0; nf < 4; nf++) {
            const int c0 = n0 + wn * 32 + nf * 8 + ((l & 3) << 1);
            float v0 = acc[mf][nf][0], v1 = acc[mf][nf][1];
            float v2 = acc[mf][nf][2], v3 = acc[mf][nf][3];
            if (EPI == 1) {
                const float b0 = __ldg(bias + c0), b1 = __ldg(bias + c0 + 1);
                v0 += b0; v1 += b1; v2 += b0; v3 += b1;
            }
            if (EPI == 2) {
                const bool u0 = __ldg(usage + c0) > 0, u1 = __ldg(usage + c0 + 1) > 0;
                v0 = u0 ? v0 * INV_TEMP : -1e9f;  v1 = u1 ? v1 * INV_TEMP : -1e9f;
                v2 = u0 ? v2 * INV_TEMP : -1e9f;  v3 = u1 ? v3 * INV_TEMP : -1e9f;
            }
            *(float2*)(C + (size_t)r0 * Ntot + c0)       = make_float2(v0, v1);
            *(float2*)(C + (size_t)(r0 + 8) * Ntot + c0) = make_float2(v2, v3);
        }
    }
}

// ---------------------------------------------------------------------------
// SIMT fp32 SGEMM for W2T = Wo @ mv^T (small, exactness helps): C[M,N]=A[M,K]@B[N,K]^T
// ---------------------------------------------------------------------------
__global__ __launch_bounds__(256, 2)
void gemm_bt_kernel(const float* __restrict__ A, const float* __restrict__ B,
                    float* __restrict__ C, int M, int N, int K)
{
    __shared__ float As[16][132];
    __shared__ float Bs[16][132];
    const int t = threadIdx.x;
    const int m0 = blockIdx.y << 7, n0 = blockIdx.x << 7;
    const int tx = t & 15, ty = t >> 4;
    float acc[8][8];
#pragma unroll
    for (int i = 0; i < 8; i++)
#pragma unroll
        for (int j = 0; j < 8; j++) acc[i][j] = 0.0f;
    const int arow = t >> 2, ac4 = (t & 3) << 2;
    for (int k0 = 0; k0 < K; k0 += 16) {
#pragma unroll
        for (int i = 0; i < 2; i++) {
            int r = arow + (i << 6);
            float4 a = *(const float4*)(A + (size_t)(m0 + r) * K + k0 + ac4);
            As[ac4 + 0][r] = a.x; As[ac4 + 1][r] = a.y; As[ac4 + 2][r] = a.z; As[ac4 + 3][r] = a.w;
            float4 b = *(const float4*)(B + (size_t)(n0 + r) * K + k0 + ac4);
            Bs[ac4 + 0][r] = b.x; Bs[ac4 + 1][r] = b.y; Bs[ac4 + 2][r] = b.z; Bs[ac4 + 3][r] = b.w;
        }
        __syncthreads();
#pragma unroll
        for (int kk = 0; kk < 16; kk++) {
            float4 a0 = *(const float4*)&As[kk][(ty << 3) + 0];
            float4 a1 = *(const float4*)&As[kk][(ty << 3) + 4];
            float4 b0 = *(const float4*)&Bs[kk][(tx << 3) + 0];
            float4 b1 = *(const float4*)&Bs[kk][(tx << 3) + 4];
            float ra[8] = {a0.x, a0.y, a0.z, a0.w, a1.x, a1.y, a1.z, a1.w};
            float rb[8] = {b0.x, b0.y, b0.z, b0.w, b1.x, b1.y, b1.z, b1.w};
#pragma unroll
            for (int i = 0; i < 8; i++)
#pragma unroll
                for (int j = 0; j < 8; j++) acc[i][j] = fmaf(ra[i], rb[j], acc[i][j]);
        }
        __syncthreads();
    }
#pragma unroll
    for (int i = 0; i < 8; i++) {
        float* cp = C + (size_t)(m0 + (ty << 3) + i) * N + n0 + (tx << 3);
        *(float4*)(cp + 0) = make_float4(acc[i][0], acc[i][1], acc[i][2], acc[i][3]);
        *(float4*)(cp + 4) = make_float4(acc[i][4], acc[i][5], acc[i][6], acc[i][7]);
    }
}

// ---------------------------------------------------------------------------
// Elementwise fp32 -> (hi, lo) bf16 split
// ---------------------------------------------------------------------------
__global__ void split_kernel(const float* __restrict__ in, __nv_bfloat16* __restrict__ oh,
                             __nv_bfloat16* __restrict__ ol, int n4)
{
    int idx = blockIdx.x * blockDim.x + threadIdx.x;
    const int stride = gridDim.x * blockDim.x;
    for (; idx < n4; idx += stride) {
        float4 v = ((const float4*)in)[idx];
        __nv_bfloat16 h0, l0, h1, l1, h2, l2, h3, l3;
        split1(v.x, h0, l0); split1(v.y, h1, l1); split1(v.z, h2, l2); split1(v.w, h3, l3);
        ((__nv_bfloat162*)oh)[idx * 2 + 0] = __halves2bfloat162(h0, h1);
        ((__nv_bfloat162*)oh)[idx * 2 + 1] = __halves2bfloat162(h2, h3);
        ((__nv_bfloat162*)ol)[idx * 2 + 0] = __halves2bfloat162(l0, l1);
        ((__nv_bfloat162*)ol)[idx * 2 + 1] = __halves2bfloat162(l2, l3);
    }
}

// ---------------------------------------------------------------------------
// Row L2-style normalize + split
// ---------------------------------------------------------------------------
__global__ void rownorm_split_kernel(const float* __restrict__ in,
                                     __nv_bfloat16* __restrict__ oh,
                                     __nv_bfloat16* __restrict__ ol)
{
    __shared__ float sh[4];
    const int row = blockIdx.x;
    const int tid = threadIdx.x;
    float4 v = ((const float4*)(in + (size_t)row * H_DIM))[tid];
    float s = v.x * v.x + v.y * v.y + v.z * v.z + v.w * v.w;
#pragma unroll
    for (int o = 16; o; o >>= 1) s += __shfl_xor_sync(0xffffffffu, s, o);
    if ((tid & 31) == 0) sh[tid >> 5] = s;
    __syncthreads();
    float r = rsqrtf(sh[0] + sh[1] + sh[2] + sh[3] + 1e-6f);
    __nv_bfloat16 h0, l0, h1, l1, h2, l2, h3, l3;
    split1(v.x * r, h0, l0); split1(v.y * r, h1, l1);
    split1(v.z * r, h2, l2); split1(v.w * r, h3, l3);
    const size_t off = (size_t)row * H_DIM + tid * 4;
    *(__nv_bfloat162*)(oh + off + 0) = __halves2bfloat162(h0, h1);
    *(__nv_bfloat162*)(oh + off + 2) = __halves2bfloat162(h2, h3);
    *(__nv_bfloat162*)(ol + off + 0) = __halves2bfloat162(l0, l1);
    *(__nv_bfloat162*)(ol + off + 2) = __halves2bfloat162(l2, l3);
}

// ---------------------------------------------------------------------------
// Softmax over M=4096 per row + bf16 hi/lo split output. 256 threads/row.
// ---------------------------------------------------------------------------
__global__ void softmax_split_kernel(const float* __restrict__ scores,
                                     __nv_bfloat16* __restrict__ oh,
                                     __nv_bfloat16* __restrict__ ol)
{
    __shared__ float sh[8];
    const int tid = threadIdx.x;
    const float4* p = (const float4*)(scores + (size_t)blockIdx.x * M_MEM);

    float4 v[4];
    float mx = -3.402823466e38f;
#pragma unroll
    for (int i = 0; i < 4; i++) {
        v[i] = p[tid + (i << 8)];
        mx = fmaxf(mx, fmaxf(fmaxf(v[i].x, v[i].y), fmaxf(v[i].z, v[i].w)));
    }
#pragma unroll
    for (int o = 16; o; o >>= 1) mx = fmaxf(mx, __shfl_xor_sync(0xffffffffu, mx, o));
    if ((tid & 31) == 0) sh[tid >> 5] = mx;
    __syncthreads();
    mx = sh[0];
#pragma unroll
    for (int i = 1; i < 8; i++) mx = fmaxf(mx, sh[i]);
    __syncthreads();

    float s = 0.0f;
#pragma unroll
    for (int i = 0; i < 4; i++) {
        v[i].x = __expf(v[i].x - mx); v[i].y = __expf(v[i].y - mx);
        v[i].z = __expf(v[i].z - mx); v[i].w = __expf(v[i].w - mx);
        s += v[i].x + v[i].y + v[i].z + v[i].w;
    }
#pragma unroll
    for (int o = 16; o; o >>= 1) s += __shfl_xor_sync(0xffffffffu, s, o);
    if ((tid & 31) == 0) sh[tid >> 5] = s;
    __syncthreads();
    float tot = sh[0];
#pragma unroll
    for (int i = 1; i < 8; i++) tot += sh[i];
    const float inv = 1.0f / tot;

#pragma unroll
    for (int i = 0; i < 4; i++) {
        const size_t off = (size_t)blockIdx.x * M_MEM + (size_t)(tid + (i << 8)) * 4;
        __nv_bfloat16 h0, l0, h1, l1, h2, l2, h3, l3;
        split1(v[i].x * inv, h0, l0); split1(v[i].y * inv, h1, l1);
        split1(v[i].z * inv, h2, l2); split1(v[i].w * inv, h3, l3);
        *(__nv_bfloat162*)(oh + off + 0) = __halves2bfloat162(h0, h1);
        *(__nv_bfloat162*)(oh + off + 2) = __halves2bfloat162(h2, h3);
        *(__nv_bfloat162*)(ol + off + 0) = __halves2bfloat162(l0, l1);
        *(__nv_bfloat162*)(ol + off + 2) = __halves2bfloat162(l2, l3);
    }
}

// ---------------------------------------------------------------------------
// Launch pipeline
// ---------------------------------------------------------------------------
extern "C" void kernel_launch(void* const* d_in, const int* in_sizes, int n_in,
                              void* d_out, int out_size)
{
    const float* hidden = (const float*)d_in[0];
    const float* mk     = (const float*)d_in[1];
    const float* mv     = (const float*)d_in[2];
    const float* Wk     = (const float*)d_in[3];
    const float* bk     = (const float*)d_in[4];
    const float* Wo     = (const float*)d_in[5];
    const float* bo     = (const float*)d_in[6];
    const int*   usage  = (const int*)d_in[7];
    float* out = (float*)d_out;

    __nv_bfloat16 *hid_hi, *hid_lo, *wk_hi, *wk_lo, *mk_hi, *mk_lo;
    __nv_bfloat16 *w2t_hi, *w2t_lo, *q_hi, *q_lo, *attn_hi, *attn_lo;
    float *w2t, *qp, *scp;
    cudaGetSymbolAddress((void**)&hid_hi, g_hid_hi);
    cudaGetSymbolAddress((void**)&hid_lo, g_hid_lo);
    cudaGetSymbolAddress((void**)&wk_hi, g_wk_hi);
    cudaGetSymbolAddress((void**)&wk_lo, g_wk_lo);
    cudaGetSymbolAddress((void**)&mk_hi, g_mk_hi);
    cudaGetSymbolAddress((void**)&mk_lo, g_mk_lo);
    cudaGetSymbolAddress((void**)&w2t, g_w2t);
    cudaGetSymbolAddress((void**)&w2t_hi, g_w2t_hi);
    cudaGetSymbolAddress((void**)&w2t_lo, g_w2t_lo);
    cudaGetSymbolAddress((void**)&qp, g_q);
    cudaGetSymbolAddress((void**)&q_hi, g_q_hi);
    cudaGetSymbolAddress((void**)&q_lo, g_q_lo);
    cudaGetSymbolAddress((void**)&scp, g_scores);
    cudaGetSymbolAddress((void**)&attn_hi, g_attn_hi);
    cudaGetSymbolAddress((void**)&attn_lo, g_attn_lo);

    cudaFuncSetAttribute(mm_gemm<1>, cudaFuncAttributeMaxDynamicSharedMemorySize, MM_SMEM);
    cudaFuncSetAttribute(mm_gemm<2>, cudaFuncAttributeMaxDynamicSharedMemorySize, MM_SMEM);

    // inputs -> bf16 hi/lo splits
    split_kernel<<<2048, 256>>>(hidden, hid_hi, hid_lo, T_TOK * H_DIM / 4);
    split_kernel<<<256, 256>>>(Wk, wk_hi, wk_lo, H_DIM * H_DIM / 4);
    rownorm_split_kernel<<<M_MEM, 128>>>(mk, mk_hi, mk_lo);

    // W2T[h,m] = sum_v Wo[h,v] * mv[m,v]  (folds out-projection into retrieval)
    gemm_bt_kernel<<<dim3(M_MEM / 128, H_DIM / 128), 256>>>(Wo, mv, w2t, H_DIM, M_MEM, H_DIM);
    split_kernel<<<2048, 256>>>(w2t, w2t_hi, w2t_lo, H_DIM * M_MEM / 4);

    // q = hidden @ Wk^T + bk  (HMMA split)
    mm_gemm<1><<<dim3(H_DIM / 128, T_TOK / 128), 256, MM_SMEM>>>(
        hid_hi, hid_lo, wk_hi, wk_lo, qp, H_DIM, H_DIM, bk, nullptr);
    rownorm_split_kernel<<<T_TOK, 128>>>(qp, q_hi, q_lo);

    // logits = mask_scale(q_n @ mk_n^T)
    mm_gemm<2><<<dim3(M_MEM / 128, T_TOK / 128), 256, MM_SMEM>>>(
        q_hi, q_lo, mk_hi, mk_lo, scp, M_MEM, H_DIM, nullptr, usage);

    // softmax rows -> attn hi/lo bf16
    softmax_split_kernel<<<T_TOK, 256>>>(scp, attn_hi, attn_lo);

    // out = attn @ W2T^T + bo
    mm_gemm<1><<<dim3(H_DIM / 128, T_TOK / 128), 256, MM_SMEM>>>(
        attn_hi, attn_lo, w2t_hi, w2t_lo, out, H_DIM, M_MEM, bo, nullptr);
}